// round 2
// baseline (speedup 1.0000x reference)
#include <cuda_runtime.h>
#include <cstdint>

// Qwen3MoeMLP: out = down( silu(x @ gate^T) * (x @ up^T) )
// T=8192, H=2048, I=768, fp32. Strategy: TF32 mma.sync with fp32 accumulate.
// Kernel 1: fused gate+up GEMM + SiLU*up epilogue -> g_hbuf [T, I] (fp32 scratch)
// Kernel 2: down GEMM -> out [T, H]

#define T_DIM 8192
#define H_DIM 2048
#define I_DIM 768

#define BK 32
#define SK 36           // padded smem row stride (floats): conflict-free + 16B aligned

// Scratch for intermediate h = silu(gate)*up. Static device global (no allocs).
__device__ __align__(256) float g_hbuf[(size_t)T_DIM * I_DIM];

__device__ __forceinline__ unsigned f2tf(float f) {
    unsigned u;
    asm("cvt.rna.tf32.f32 %0, %1;" : "=r"(u) : "f"(f));
    return u;
}

__device__ __forceinline__ void cp16(void* s, const void* g) {
    unsigned sa = (unsigned)__cvta_generic_to_shared(s);
    asm volatile("cp.async.cg.shared.global [%0], [%1], 16;\n" :: "r"(sa), "l"(g));
}
__device__ __forceinline__ void cp_commit() {
    asm volatile("cp.async.commit_group;\n" ::);
}
template <int N>
__device__ __forceinline__ void cp_wait() {
    asm volatile("cp.async.wait_group %0;\n" :: "n"(N));
}

__device__ __forceinline__ void mma8(float* c, const unsigned* a, const unsigned* b) {
    asm volatile(
        "mma.sync.aligned.m16n8k8.row.col.f32.tf32.tf32.f32 "
        "{%0,%1,%2,%3}, {%4,%5,%6,%7}, {%8,%9}, {%0,%1,%2,%3};\n"
        : "+f"(c[0]), "+f"(c[1]), "+f"(c[2]), "+f"(c[3])
        : "r"(a[0]), "r"(a[1]), "r"(a[2]), "r"(a[3]), "r"(b[0]), "r"(b[1]));
}

// ============================================================================
// Kernel 1: gate+up fused.  C tile: BM=128 x BN=64 (per projection).
// 8 warps: wm = warp&3 (M, 4x32), wn = warp>>2 (N, 2x32).
// Each warp: 2 m16 tiles x 4 n8 tiles per projection.
// ============================================================================
__global__ void __launch_bounds__(256, 2)
gateup_kernel(const float* __restrict__ X,
              const float* __restrict__ Wg,
              const float* __restrict__ Wu)
{
    extern __shared__ float smp[];
    float* As = smp;                     // [2][128][SK]
    float* Bg = smp + 2 * 128 * SK;      // [2][64][SK]
    float* Bu = Bg + 2 * 64 * SK;        // [2][64][SK]

    const int tid  = threadIdx.x;
    const int lane = tid & 31;
    const int warp = tid >> 5;
    const int wm = warp & 3;
    const int wn = warp >> 2;
    const int g  = lane >> 2;            // groupID
    const int tg = lane & 3;             // threadID_in_group

    const int bm = blockIdx.x * 128;
    const int bn = blockIdx.y * 64;

    const int lr = tid >> 3;             // 0..31 (load row)
    const int lc = (tid & 7) * 4;        // 0..28 (load col, floats)

    float accg[2][4][4];
    float accu[2][4][4];
#pragma unroll
    for (int i = 0; i < 2; i++)
#pragma unroll
        for (int j = 0; j < 4; j++)
#pragma unroll
            for (int k = 0; k < 4; k++) { accg[i][j][k] = 0.f; accu[i][j][k] = 0.f; }

    auto load_stage = [&](int st, int kt) {
        const int k0 = kt * BK;
        float* as = As + st * 128 * SK;
#pragma unroll
        for (int i = 0; i < 4; i++) {
            const int r = lr + 32 * i;
            cp16(as + r * SK + lc, X + (size_t)(bm + r) * H_DIM + k0 + lc);
        }
        float* bgs = Bg + st * 64 * SK;
        float* bus = Bu + st * 64 * SK;
#pragma unroll
        for (int i = 0; i < 2; i++) {
            const int r = lr + 32 * i;
            cp16(bgs + r * SK + lc, Wg + (size_t)(bn + r) * H_DIM + k0 + lc);
            cp16(bus + r * SK + lc, Wu + (size_t)(bn + r) * H_DIM + k0 + lc);
        }
    };

    auto compute = [&](int st) {
        const float* as  = As + st * 128 * SK;
        const float* bgs = Bg + st * 64 * SK;
        const float* bus = Bu + st * 64 * SK;
#pragma unroll
        for (int k8 = 0; k8 < BK / 8; k8++) {
            const int kk = k8 * 8;
            unsigned a[2][4];
#pragma unroll
            for (int t = 0; t < 2; t++) {
                const float* ap = as + (size_t)(wm * 32 + t * 16) * SK + kk;
                a[t][0] = f2tf(ap[(size_t)g * SK + tg]);
                a[t][1] = f2tf(ap[(size_t)(g + 8) * SK + tg]);
                a[t][2] = f2tf(ap[(size_t)g * SK + tg + 4]);
                a[t][3] = f2tf(ap[(size_t)(g + 8) * SK + tg + 4]);
            }
#pragma unroll
            for (int t = 0; t < 4; t++) {
                const int n = wn * 32 + t * 8 + g;
                unsigned bgf[2], buf2[2];
                bgf[0]  = f2tf(bgs[(size_t)n * SK + kk + tg]);
                bgf[1]  = f2tf(bgs[(size_t)n * SK + kk + tg + 4]);
                buf2[0] = f2tf(bus[(size_t)n * SK + kk + tg]);
                buf2[1] = f2tf(bus[(size_t)n * SK + kk + tg + 4]);
#pragma unroll
                for (int m = 0; m < 2; m++) {
                    mma8(accg[m][t], a[m], bgf);
                    mma8(accu[m][t], a[m], buf2);
                }
            }
        }
    };

    const int KT = H_DIM / BK;  // 64
    load_stage(0, 0);
    cp_commit();

    for (int kt = 0; kt < KT; ++kt) {
        if (kt + 1 < KT) {
            load_stage((kt + 1) & 1, kt + 1);
            cp_commit();
            cp_wait<1>();
        } else {
            cp_wait<0>();
        }
        __syncthreads();
        compute(kt & 1);
        __syncthreads();
    }

    // Epilogue: h = silu(gate) * up  -> g_hbuf
#pragma unroll
    for (int tm = 0; tm < 2; tm++) {
#pragma unroll
        for (int tn = 0; tn < 4; tn++) {
            const int r0 = bm + wm * 32 + tm * 16 + g;
            const int c0 = bn + wn * 32 + tn * 8 + 2 * tg;
            float h[4];
#pragma unroll
            for (int i = 0; i < 4; i++) {
                const float gv = accg[tm][tn][i];
                const float uv = accu[tm][tn][i];
                h[i] = gv * uv / (1.0f + __expf(-gv));
            }
            *(float2*)(g_hbuf + (size_t)r0 * I_DIM + c0)       = make_float2(h[0], h[1]);
            *(float2*)(g_hbuf + (size_t)(r0 + 8) * I_DIM + c0) = make_float2(h[2], h[3]);
        }
    }
}

// ============================================================================
// Kernel 2: down projection.  C tile: BM=128 x BN=128.
// 8 warps: wm = warp&3 (M, 4x32), wn = warp>>2 (N, 2x64).
// Each warp: 2 m16 tiles x 8 n8 tiles.
// ============================================================================
__global__ void __launch_bounds__(256, 2)
down_kernel(const float* __restrict__ Wd, float* __restrict__ Out)
{
    extern __shared__ float smp[];
    float* As = smp;                     // [2][128][SK]
    float* Bs = smp + 2 * 128 * SK;      // [2][128][SK]

    const int tid  = threadIdx.x;
    const int lane = tid & 31;
    const int warp = tid >> 5;
    const int wm = warp & 3;
    const int wn = warp >> 2;
    const int g  = lane >> 2;
    const int tg = lane & 3;

    const int bm = blockIdx.x * 128;
    const int bn = blockIdx.y * 128;

    const int lr = tid >> 3;
    const int lc = (tid & 7) * 4;

    float acc[2][8][4];
#pragma unroll
    for (int i = 0; i < 2; i++)
#pragma unroll
        for (int j = 0; j < 8; j++)
#pragma unroll
            for (int k = 0; k < 4; k++) acc[i][j][k] = 0.f;

    auto load_stage = [&](int st, int kt) {
        const int k0 = kt * BK;
        float* as = As + st * 128 * SK;
        float* bs = Bs + st * 128 * SK;
#pragma unroll
        for (int i = 0; i < 4; i++) {
            const int r = lr + 32 * i;
            cp16(as + r * SK + lc, g_hbuf + (size_t)(bm + r) * I_DIM + k0 + lc);
            cp16(bs + r * SK + lc, Wd + (size_t)(bn + r) * I_DIM + k0 + lc);
        }
    };

    auto compute = [&](int st) {
        const float* as = As + st * 128 * SK;
        const float* bs = Bs + st * 128 * SK;
#pragma unroll
        for (int k8 = 0; k8 < BK / 8; k8++) {
            const int kk = k8 * 8;
            unsigned a[2][4];
#pragma unroll
            for (int t = 0; t < 2; t++) {
                const float* ap = as + (size_t)(wm * 32 + t * 16) * SK + kk;
                a[t][0] = f2tf(ap[(size_t)g * SK + tg]);
                a[t][1] = f2tf(ap[(size_t)(g + 8) * SK + tg]);
                a[t][2] = f2tf(ap[(size_t)g * SK + tg + 4]);
                a[t][3] = f2tf(ap[(size_t)(g + 8) * SK + tg + 4]);
            }
            unsigned b[8][2];
#pragma unroll
            for (int t = 0; t < 8; t++) {
                const int n = wn * 64 + t * 8 + g;
                b[t][0] = f2tf(bs[(size_t)n * SK + kk + tg]);
                b[t][1] = f2tf(bs[(size_t)n * SK + kk + tg + 4]);
            }
#pragma unroll
            for (int t = 0; t < 8; t++)
#pragma unroll
                for (int m = 0; m < 2; m++)
                    mma8(acc[m][t], a[m], b[t]);
        }
    };

    const int KT = I_DIM / BK;  // 24
    load_stage(0, 0);
    cp_commit();

    for (int kt = 0; kt < KT; ++kt) {
        if (kt + 1 < KT) {
            load_stage((kt + 1) & 1, kt + 1);
            cp_commit();
            cp_wait<1>();
        } else {
            cp_wait<0>();
        }
        __syncthreads();
        compute(kt & 1);
        __syncthreads();
    }

#pragma unroll
    for (int tm = 0; tm < 2; tm++) {
#pragma unroll
        for (int tn = 0; tn < 8; tn++) {
            const int r0 = bm + wm * 32 + tm * 16 + g;
            const int c0 = bn + wn * 64 + tn * 8 + 2 * tg;
            *(float2*)(Out + (size_t)r0 * H_DIM + c0) =
                make_float2(acc[tm][tn][0], acc[tm][tn][1]);
            *(float2*)(Out + (size_t)(r0 + 8) * H_DIM + c0) =
                make_float2(acc[tm][tn][2], acc[tm][tn][3]);
        }
    }
}

// ============================================================================
// Launch
// ============================================================================
extern "C" void kernel_launch(void* const* d_in, const int* in_sizes, int n_in,
                              void* d_out, int out_size)
{
    const float* x  = (const float*)d_in[0];
    const float* wg = (const float*)d_in[1];
    const float* wu = (const float*)d_in[2];
    const float* wd = (const float*)d_in[3];
    float* out = (float*)d_out;

    const int smem_bytes = (2 * 128 * SK + 2 * 64 * SK * 2) * (int)sizeof(float); // 73728
    cudaFuncSetAttribute(gateup_kernel, cudaFuncAttributeMaxDynamicSharedMemorySize, smem_bytes);
    cudaFuncSetAttribute(down_kernel,   cudaFuncAttributeMaxDynamicSharedMemorySize, smem_bytes);

    dim3 grid1(T_DIM / 128, I_DIM / 64);   // 64 x 12
    gateup_kernel<<<grid1, 256, smem_bytes>>>(x, wg, wu);

    dim3 grid2(T_DIM / 128, H_DIM / 128);  // 64 x 16
    down_kernel<<<grid2, 256, smem_bytes>>>(wd, out);
}

// round 3
// speedup vs baseline: 1.5526x; 1.5526x over previous
#include <cuda_runtime.h>
#include <cstdint>

// Qwen3MoeMLP: out = down( silu(x @ gate^T) * (x @ up^T) )
// T=8192, H=2048, I=768, fp32. Strategy: TF32 mma.sync with fp32 accumulate.
// Kernel 1: fused gate+up GEMM + SiLU*up epilogue -> g_hbuf [T, I] (fp32 scratch)
// Kernel 2: down GEMM -> out [T, H]

#define T_DIM 8192
#define H_DIM 2048
#define I_DIM 768

#define BK 32
#define SK 36           // padded smem row stride (floats): conflict-free + 16B aligned

// Scratch for intermediate h = silu(gate)*up. Static device global (no allocs).
__device__ __align__(256) float g_hbuf[(size_t)T_DIM * I_DIM];

__device__ __forceinline__ unsigned f2tf(float f) {
    unsigned u;
    asm("cvt.rna.tf32.f32 %0, %1;" : "=r"(u) : "f"(f));
    return u;
}

__device__ __forceinline__ void cp16(void* s, const void* g) {
    unsigned sa = (unsigned)__cvta_generic_to_shared(s);
    asm volatile("cp.async.cg.shared.global [%0], [%1], 16;\n" :: "r"(sa), "l"(g));
}
__device__ __forceinline__ void cp_commit() {
    asm volatile("cp.async.commit_group;\n" ::);
}
template <int N>
__device__ __forceinline__ void cp_wait() {
    asm volatile("cp.async.wait_group %0;\n" :: "n"(N));
}

__device__ __forceinline__ void mma8(float* c, const unsigned* a, const unsigned* b) {
    asm volatile(
        "mma.sync.aligned.m16n8k8.row.col.f32.tf32.tf32.f32 "
        "{%0,%1,%2,%3}, {%4,%5,%6,%7}, {%8,%9}, {%0,%1,%2,%3};\n"
        : "+f"(c[0]), "+f"(c[1]), "+f"(c[2]), "+f"(c[3])
        : "r"(a[0]), "r"(a[1]), "r"(a[2]), "r"(a[3]), "r"(b[0]), "r"(b[1]));
}

// ============================================================================
// Kernel 1: gate+up fused.  C tile: BM=128 x BN=64 (per projection).
// 8 warps: wm = warp&3 (M, 4x32), wn = warp>>2 (N, 2x32).
// Each warp: 2 m16 tiles x 4 n8 tiles per projection.
// ============================================================================
__global__ void __launch_bounds__(256, 2)
gateup_kernel(const float* __restrict__ X,
              const float* __restrict__ Wg,
              const float* __restrict__ Wu)
{
    extern __shared__ float smp[];
    float* As = smp;                     // [2][128][SK]
    float* Bg = smp + 2 * 128 * SK;      // [2][64][SK]
    float* Bu = Bg + 2 * 64 * SK;        // [2][64][SK]

    const int tid  = threadIdx.x;
    const int lane = tid & 31;
    const int warp = tid >> 5;
    const int wm = warp & 3;
    const int wn = warp >> 2;
    const int g  = lane >> 2;            // groupID
    const int tg = lane & 3;             // threadID_in_group

    const int bm = blockIdx.x * 128;
    const int bn = blockIdx.y * 64;

    const int lr = tid >> 3;             // 0..31 (load row)
    const int lc = (tid & 7) * 4;        // 0..28 (load col, floats)

    float accg[2][4][4];
    float accu[2][4][4];
#pragma unroll
    for (int i = 0; i < 2; i++)
#pragma unroll
        for (int j = 0; j < 4; j++)
#pragma unroll
            for (int k = 0; k < 4; k++) { accg[i][j][k] = 0.f; accu[i][j][k] = 0.f; }

    auto load_stage = [&](int st, int kt) {
        const int k0 = kt * BK;
        float* as = As + st * 128 * SK;
#pragma unroll
        for (int i = 0; i < 4; i++) {
            const int r = lr + 32 * i;
            cp16(as + r * SK + lc, X + (size_t)(bm + r) * H_DIM + k0 + lc);
        }
        float* bgs = Bg + st * 64 * SK;
        float* bus = Bu + st * 64 * SK;
#pragma unroll
        for (int i = 0; i < 2; i++) {
            const int r = lr + 32 * i;
            cp16(bgs + r * SK + lc, Wg + (size_t)(bn + r) * H_DIM + k0 + lc);
            cp16(bus + r * SK + lc, Wu + (size_t)(bn + r) * H_DIM + k0 + lc);
        }
    };

    auto compute = [&](int st) {
        const float* as  = As + st * 128 * SK;
        const float* bgs = Bg + st * 64 * SK;
        const float* bus = Bu + st * 64 * SK;
#pragma unroll
        for (int k8 = 0; k8 < BK / 8; k8++) {
            const int kk = k8 * 8;
            unsigned a[2][4];
#pragma unroll
            for (int t = 0; t < 2; t++) {
                const float* ap = as + (size_t)(wm * 32 + t * 16) * SK + kk;
                a[t][0] = f2tf(ap[(size_t)g * SK + tg]);
                a[t][1] = f2tf(ap[(size_t)(g + 8) * SK + tg]);
                a[t][2] = f2tf(ap[(size_t)g * SK + tg + 4]);
                a[t][3] = f2tf(ap[(size_t)(g + 8) * SK + tg + 4]);
            }
#pragma unroll
            for (int t = 0; t < 4; t++) {
                const int n = wn * 32 + t * 8 + g;
                unsigned bgf[2], buf2[2];
                bgf[0]  = f2tf(bgs[(size_t)n * SK + kk + tg]);
                bgf[1]  = f2tf(bgs[(size_t)n * SK + kk + tg + 4]);
                buf2[0] = f2tf(bus[(size_t)n * SK + kk + tg]);
                buf2[1] = f2tf(bus[(size_t)n * SK + kk + tg + 4]);
#pragma unroll
                for (int m = 0; m < 2; m++) {
                    mma8(accg[m][t], a[m], bgf);
                    mma8(accu[m][t], a[m], buf2);
                }
            }
        }
    };

    const int KT = H_DIM / BK;  // 64
    load_stage(0, 0);
    cp_commit();

    for (int kt = 0; kt < KT; ++kt) {
        if (kt + 1 < KT) {
            load_stage((kt + 1) & 1, kt + 1);
            cp_commit();
            cp_wait<1>();
        } else {
            cp_wait<0>();
        }
        __syncthreads();
        compute(kt & 1);
        __syncthreads();
    }

    // Epilogue: h = silu(gate) * up  -> g_hbuf
#pragma unroll
    for (int tm = 0; tm < 2; tm++) {
#pragma unroll
        for (int tn = 0; tn < 4; tn++) {
            const int r0 = bm + wm * 32 + tm * 16 + g;
            const int c0 = bn + wn * 32 + tn * 8 + 2 * tg;
            float h[4];
#pragma unroll
            for (int i = 0; i < 4; i++) {
                const float gv = accg[tm][tn][i];
                const float uv = accu[tm][tn][i];
                h[i] = gv * uv / (1.0f + __expf(-gv));
            }
            *(float2*)(g_hbuf + (size_t)r0 * I_DIM + c0)       = make_float2(h[0], h[1]);
            *(float2*)(g_hbuf + (size_t)(r0 + 8) * I_DIM + c0) = make_float2(h[2], h[3]);
        }
    }
}

// ============================================================================
// Kernel 2: down projection.  C tile: BM=128 x BN=128.
// 8 warps: wm = warp&3 (M, 4x32), wn = warp>>2 (N, 2x64).
// Each warp: 2 m16 tiles x 8 n8 tiles.
// ============================================================================
__global__ void __launch_bounds__(256, 2)
down_kernel(const float* __restrict__ Wd, float* __restrict__ Out)
{
    extern __shared__ float smp[];
    float* As = smp;                     // [2][128][SK]
    float* Bs = smp + 2 * 128 * SK;      // [2][128][SK]

    const int tid  = threadIdx.x;
    const int lane = tid & 31;
    const int warp = tid >> 5;
    const int wm = warp & 3;
    const int wn = warp >> 2;
    const int g  = lane >> 2;
    const int tg = lane & 3;

    const int bm = blockIdx.x * 128;
    const int bn = blockIdx.y * 128;

    const int lr = tid >> 3;
    const int lc = (tid & 7) * 4;

    float acc[2][8][4];
#pragma unroll
    for (int i = 0; i < 2; i++)
#pragma unroll
        for (int j = 0; j < 8; j++)
#pragma unroll
            for (int k = 0; k < 4; k++) acc[i][j][k] = 0.f;

    auto load_stage = [&](int st, int kt) {
        const int k0 = kt * BK;
        float* as = As + st * 128 * SK;
        float* bs = Bs + st * 128 * SK;
#pragma unroll
        for (int i = 0; i < 4; i++) {
            const int r = lr + 32 * i;
            cp16(as + r * SK + lc, g_hbuf + (size_t)(bm + r) * I_DIM + k0 + lc);
            cp16(bs + r * SK + lc, Wd + (size_t)(bn + r) * I_DIM + k0 + lc);
        }
    };

    auto compute = [&](int st) {
        const float* as = As + st * 128 * SK;
        const float* bs = Bs + st * 128 * SK;
#pragma unroll
        for (int k8 = 0; k8 < BK / 8; k8++) {
            const int kk = k8 * 8;
            unsigned a[2][4];
#pragma unroll
            for (int t = 0; t < 2; t++) {
                const float* ap = as + (size_t)(wm * 32 + t * 16) * SK + kk;
                a[t][0] = f2tf(ap[(size_t)g * SK + tg]);
                a[t][1] = f2tf(ap[(size_t)(g + 8) * SK + tg]);
                a[t][2] = f2tf(ap[(size_t)g * SK + tg + 4]);
                a[t][3] = f2tf(ap[(size_t)(g + 8) * SK + tg + 4]);
            }
            unsigned b[8][2];
#pragma unroll
            for (int t = 0; t < 8; t++) {
                const int n = wn * 64 + t * 8 + g;
                b[t][0] = f2tf(bs[(size_t)n * SK + kk + tg]);
                b[t][1] = f2tf(bs[(size_t)n * SK + kk + tg + 4]);
            }
#pragma unroll
            for (int t = 0; t < 8; t++)
#pragma unroll
                for (int m = 0; m < 2; m++)
                    mma8(acc[m][t], a[m], b[t]);
        }
    };

    const int KT = I_DIM / BK;  // 24
    load_stage(0, 0);
    cp_commit();

    for (int kt = 0; kt < KT; ++kt) {
        if (kt + 1 < KT) {
            load_stage((kt + 1) & 1, kt + 1);
            cp_commit();
            cp_wait<1>();
        } else {
            cp_wait<0>();
        }
        __syncthreads();
        compute(kt & 1);
        __syncthreads();
    }

#pragma unroll
    for (int tm = 0; tm < 2; tm++) {
#pragma unroll
        for (int tn = 0; tn < 8; tn++) {
            const int r0 = bm + wm * 32 + tm * 16 + g;
            const int c0 = bn + wn * 64 + tn * 8 + 2 * tg;
            *(float2*)(Out + (size_t)r0 * H_DIM + c0) =
                make_float2(acc[tm][tn][0], acc[tm][tn][1]);
            *(float2*)(Out + (size_t)(r0 + 8) * H_DIM + c0) =
                make_float2(acc[tm][tn][2], acc[tm][tn][3]);
        }
    }
}

// ============================================================================
// Launch
// ============================================================================
extern "C" void kernel_launch(void* const* d_in, const int* in_sizes, int n_in,
                              void* d_out, int out_size)
{
    const float* x  = (const float*)d_in[0];
    const float* wg = (const float*)d_in[1];
    const float* wu = (const float*)d_in[2];
    const float* wd = (const float*)d_in[3];
    float* out = (float*)d_out;

    const int smem_bytes = (2 * 128 * SK + 2 * 64 * SK * 2) * (int)sizeof(float); // 73728
    cudaFuncSetAttribute(gateup_kernel, cudaFuncAttributeMaxDynamicSharedMemorySize, smem_bytes);
    cudaFuncSetAttribute(down_kernel,   cudaFuncAttributeMaxDynamicSharedMemorySize, smem_bytes);

    dim3 grid1(T_DIM / 128, I_DIM / 64);   // 64 x 12
    gateup_kernel<<<grid1, 256, smem_bytes>>>(x, wg, wu);

    dim3 grid2(T_DIM / 128, H_DIM / 128);  // 64 x 16
    down_kernel<<<grid2, 256, smem_bytes>>>(wd, out);
}

// round 6
// speedup vs baseline: 1.6094x; 1.0366x over previous
#include <cuda_runtime.h>
#include <cstdint>

// Qwen3MoeMLP: out = down( silu(x @ gate^T) * (x @ up^T) )
// T=8192, H=2048, I=768, fp32. TF32 mma.sync with fp32 accumulate.
// tcgen05 is NOT available in this build path (PTX target is sm_103, non-'a').
// Strategy: pre-round all operands to the tf32 grid ONCE (prep kernel), so the
// GEMM mainloops are pure LDS + HMMA (no cvt instructions, no cvt latency).

#define T_DIM 8192
#define H_DIM 2048
#define I_DIM 768

#define BK 32
#define SK 36           // padded smem row stride (floats): conflict-free + 16B aligned

// Static device scratch (no allocations allowed).
__device__ __align__(256) float g_xr [(size_t)T_DIM * H_DIM];   // rounded X
__device__ __align__(256) float g_wgr[(size_t)I_DIM * H_DIM];   // rounded gate_w
__device__ __align__(256) float g_wur[(size_t)I_DIM * H_DIM];   // rounded up_w
__device__ __align__(256) float g_wdr[(size_t)H_DIM * I_DIM];   // rounded down_w
__device__ __align__(256) float g_hbuf[(size_t)T_DIM * I_DIM];  // rounded h

__device__ __forceinline__ float f2tf(float f) {
    unsigned u;
    asm("cvt.rna.tf32.f32 %0, %1;" : "=r"(u) : "f"(f));
    return __uint_as_float(u);
}

__device__ __forceinline__ void cp16(void* s, const void* g) {
    unsigned sa = (unsigned)__cvta_generic_to_shared(s);
    asm volatile("cp.async.cg.shared.global [%0], [%1], 16;\n" :: "r"(sa), "l"(g));
}
__device__ __forceinline__ void cp_commit() {
    asm volatile("cp.async.commit_group;\n" ::);
}
template <int N>
__device__ __forceinline__ void cp_wait() {
    asm volatile("cp.async.wait_group %0;\n" :: "n"(N));
}

__device__ __forceinline__ void mma8(float* c, const unsigned* a, const unsigned* b) {
    asm volatile(
        "mma.sync.aligned.m16n8k8.row.col.f32.tf32.tf32.f32 "
        "{%0,%1,%2,%3}, {%4,%5,%6,%7}, {%8,%9}, {%0,%1,%2,%3};\n"
        : "+f"(c[0]), "+f"(c[1]), "+f"(c[2]), "+f"(c[3])
        : "r"(a[0]), "r"(a[1]), "r"(a[2]), "r"(a[3]), "r"(b[0]), "r"(b[1]));
}

__device__ __forceinline__ unsigned lds_u(const float* p) {
    return __float_as_uint(*p);
}

// ============================================================================
// Prep kernel: round fp32 -> tf32 grid (RNA) for all GEMM operands.
// ============================================================================
__global__ void __launch_bounds__(256)
prep_kernel(const float* __restrict__ X,  const float* __restrict__ Wg,
            const float* __restrict__ Wu, const float* __restrict__ Wd)
{
    const size_t NX = (size_t)T_DIM * H_DIM / 4;   // in float4
    const size_t NW = (size_t)I_DIM * H_DIM / 4;
    const size_t total = NX + 3 * NW;
    const size_t stride = (size_t)gridDim.x * blockDim.x;

    for (size_t i = (size_t)blockIdx.x * blockDim.x + threadIdx.x; i < total; i += stride) {
        const float4* src;
        float4* dst;
        size_t j;
        if (i < NX)              { src = (const float4*)X;  dst = (float4*)g_xr;  j = i; }
        else if (i < NX + NW)    { src = (const float4*)Wg; dst = (float4*)g_wgr; j = i - NX; }
        else if (i < NX + 2*NW)  { src = (const float4*)Wu; dst = (float4*)g_wur; j = i - NX - NW; }
        else                     { src = (const float4*)Wd; dst = (float4*)g_wdr; j = i - NX - 2*NW; }
        float4 v = src[j];
        dst[j] = make_float4(f2tf(v.x), f2tf(v.y), f2tf(v.z), f2tf(v.w));
    }
}

// ============================================================================
// Kernel 1: gate+up fused.  C tile: BM=128 x BN=64 (per projection).
// 8 warps: wm = warp&3 (M, 4x32), wn = warp>>2 (N, 2x32).
// ============================================================================
__global__ void __launch_bounds__(256, 2)
gateup_kernel()
{
    extern __shared__ float smp[];
    float* As = smp;                     // [2][128][SK]
    float* Bg = smp + 2 * 128 * SK;      // [2][64][SK]
    float* Bu = Bg + 2 * 64 * SK;        // [2][64][SK]

    const int tid  = threadIdx.x;
    const int lane = tid & 31;
    const int warp = tid >> 5;
    const int wm = warp & 3;
    const int wn = warp >> 2;
    const int g  = lane >> 2;
    const int tg = lane & 3;

    const int bm = blockIdx.x * 128;
    const int bn = blockIdx.y * 64;

    const int lr = tid >> 3;
    const int lc = (tid & 7) * 4;

    float accg[2][4][4];
    float accu[2][4][4];
#pragma unroll
    for (int i = 0; i < 2; i++)
#pragma unroll
        for (int j = 0; j < 4; j++)
#pragma unroll
            for (int k = 0; k < 4; k++) { accg[i][j][k] = 0.f; accu[i][j][k] = 0.f; }

    auto load_stage = [&](int st, int kt) {
        const int k0 = kt * BK;
        float* as = As + st * 128 * SK;
#pragma unroll
        for (int i = 0; i < 4; i++) {
            const int r = lr + 32 * i;
            cp16(as + r * SK + lc, g_xr + (size_t)(bm + r) * H_DIM + k0 + lc);
        }
        float* bgs = Bg + st * 64 * SK;
        float* bus = Bu + st * 64 * SK;
#pragma unroll
        for (int i = 0; i < 2; i++) {
            const int r = lr + 32 * i;
            cp16(bgs + r * SK + lc, g_wgr + (size_t)(bn + r) * H_DIM + k0 + lc);
            cp16(bus + r * SK + lc, g_wur + (size_t)(bn + r) * H_DIM + k0 + lc);
        }
    };

    auto compute = [&](int st) {
        const float* as  = As + st * 128 * SK;
        const float* bgs = Bg + st * 64 * SK;
        const float* bus = Bu + st * 64 * SK;
#pragma unroll
        for (int k8 = 0; k8 < BK / 8; k8++) {
            const int kk = k8 * 8;
            unsigned a[2][4];
#pragma unroll
            for (int t = 0; t < 2; t++) {
                const float* ap = as + (size_t)(wm * 32 + t * 16) * SK + kk;
                a[t][0] = lds_u(ap + (size_t)g * SK + tg);
                a[t][1] = lds_u(ap + (size_t)(g + 8) * SK + tg);
                a[t][2] = lds_u(ap + (size_t)g * SK + tg + 4);
                a[t][3] = lds_u(ap + (size_t)(g + 8) * SK + tg + 4);
            }
#pragma unroll
            for (int t = 0; t < 4; t++) {
                const int n = wn * 32 + t * 8 + g;
                unsigned bgf[2], buf2[2];
                bgf[0]  = lds_u(bgs + (size_t)n * SK + kk + tg);
                bgf[1]  = lds_u(bgs + (size_t)n * SK + kk + tg + 4);
                buf2[0] = lds_u(bus + (size_t)n * SK + kk + tg);
                buf2[1] = lds_u(bus + (size_t)n * SK + kk + tg + 4);
#pragma unroll
                for (int m = 0; m < 2; m++) {
                    mma8(accg[m][t], a[m], bgf);
                    mma8(accu[m][t], a[m], buf2);
                }
            }
        }
    };

    const int KT = H_DIM / BK;  // 64
    load_stage(0, 0);
    cp_commit();

    for (int kt = 0; kt < KT; ++kt) {
        if (kt + 1 < KT) {
            load_stage((kt + 1) & 1, kt + 1);
            cp_commit();
            cp_wait<1>();
        } else {
            cp_wait<0>();
        }
        __syncthreads();
        compute(kt & 1);
        __syncthreads();
    }

    // Epilogue: h = silu(gate) * up, rounded to tf32 grid -> g_hbuf
#pragma unroll
    for (int tm = 0; tm < 2; tm++) {
#pragma unroll
        for (int tn = 0; tn < 4; tn++) {
            const int r0 = bm + wm * 32 + tm * 16 + g;
            const int c0 = bn + wn * 32 + tn * 8 + 2 * tg;
            float h[4];
#pragma unroll
            for (int i = 0; i < 4; i++) {
                const float gv = accg[tm][tn][i];
                const float uv = accu[tm][tn][i];
                h[i] = f2tf(gv * uv / (1.0f + __expf(-gv)));
            }
            *(float2*)(g_hbuf + (size_t)r0 * I_DIM + c0)       = make_float2(h[0], h[1]);
            *(float2*)(g_hbuf + (size_t)(r0 + 8) * I_DIM + c0) = make_float2(h[2], h[3]);
        }
    }
}

// ============================================================================
// Kernel 2: down projection.  C tile: BM=128 x BN=128.
// 8 warps: wm = warp&3 (M, 4x32), wn = warp>>2 (N, 2x64).
// ============================================================================
__global__ void __launch_bounds__(256, 2)
down_kernel(float* __restrict__ Out)
{
    extern __shared__ float smp[];
    float* As = smp;                     // [2][128][SK]
    float* Bs = smp + 2 * 128 * SK;      // [2][128][SK]

    const int tid  = threadIdx.x;
    const int lane = tid & 31;
    const int warp = tid >> 5;
    const int wm = warp & 3;
    const int wn = warp >> 2;
    const int g  = lane >> 2;
    const int tg = lane & 3;

    const int bm = blockIdx.x * 128;
    const int bn = blockIdx.y * 128;

    const int lr = tid >> 3;
    const int lc = (tid & 7) * 4;

    float acc[2][8][4];
#pragma unroll
    for (int i = 0; i < 2; i++)
#pragma unroll
        for (int j = 0; j < 8; j++)
#pragma unroll
            for (int k = 0; k < 4; k++) acc[i][j][k] = 0.f;

    auto load_stage = [&](int st, int kt) {
        const int k0 = kt * BK;
        float* as = As + st * 128 * SK;
        float* bs = Bs + st * 128 * SK;
#pragma unroll
        for (int i = 0; i < 4; i++) {
            const int r = lr + 32 * i;
            cp16(as + r * SK + lc, g_hbuf + (size_t)(bm + r) * I_DIM + k0 + lc);
            cp16(bs + r * SK + lc, g_wdr  + (size_t)(bn + r) * I_DIM + k0 + lc);
        }
    };

    auto compute = [&](int st) {
        const float* as = As + st * 128 * SK;
        const float* bs = Bs + st * 128 * SK;
#pragma unroll
        for (int k8 = 0; k8 < BK / 8; k8++) {
            const int kk = k8 * 8;
            unsigned a[2][4];
#pragma unroll
            for (int t = 0; t < 2; t++) {
                const float* ap = as + (size_t)(wm * 32 + t * 16) * SK + kk;
                a[t][0] = lds_u(ap + (size_t)g * SK + tg);
                a[t][1] = lds_u(ap + (size_t)(g + 8) * SK + tg);
                a[t][2] = lds_u(ap + (size_t)g * SK + tg + 4);
                a[t][3] = lds_u(ap + (size_t)(g + 8) * SK + tg + 4);
            }
            unsigned b[8][2];
#pragma unroll
            for (int t = 0; t < 8; t++) {
                const int n = wn * 64 + t * 8 + g;
                b[t][0] = lds_u(bs + (size_t)n * SK + kk + tg);
                b[t][1] = lds_u(bs + (size_t)n * SK + kk + tg + 4);
            }
#pragma unroll
            for (int t = 0; t < 8; t++)
#pragma unroll
                for (int m = 0; m < 2; m++)
                    mma8(acc[m][t], a[m], b[t]);
        }
    };

    const int KT = I_DIM / BK;  // 24
    load_stage(0, 0);
    cp_commit();

    for (int kt = 0; kt < KT; ++kt) {
        if (kt + 1 < KT) {
            load_stage((kt + 1) & 1, kt + 1);
            cp_commit();
            cp_wait<1>();
        } else {
            cp_wait<0>();
        }
        __syncthreads();
        compute(kt & 1);
        __syncthreads();
    }

#pragma unroll
    for (int tm = 0; tm < 2; tm++) {
#pragma unroll
        for (int tn = 0; tn < 8; tn++) {
            const int r0 = bm + wm * 32 + tm * 16 + g;
            const int c0 = bn + wn * 64 + tn * 8 + 2 * tg;
            *(float2*)(Out + (size_t)r0 * H_DIM + c0) =
                make_float2(acc[tm][tn][0], acc[tm][tn][1]);
            *(float2*)(Out + (size_t)(r0 + 8) * H_DIM + c0) =
                make_float2(acc[tm][tn][2], acc[tm][tn][3]);
        }
    }
}

// ============================================================================
// Launch
// ============================================================================
extern "C" void kernel_launch(void* const* d_in, const int* in_sizes, int n_in,
                              void* d_out, int out_size)
{
    const float* x  = (const float*)d_in[0];
    const float* wg = (const float*)d_in[1];
    const float* wu = (const float*)d_in[2];
    const float* wd = (const float*)d_in[3];
    float* out = (float*)d_out;

    const int smem_bytes = (2 * 128 * SK + 2 * 64 * SK * 2) * (int)sizeof(float); // 73728
    cudaFuncSetAttribute(gateup_kernel, cudaFuncAttributeMaxDynamicSharedMemorySize, smem_bytes);
    cudaFuncSetAttribute(down_kernel,   cudaFuncAttributeMaxDynamicSharedMemorySize, smem_bytes);

    prep_kernel<<<2048, 256>>>(x, wg, wu, wd);

    dim3 grid1(T_DIM / 128, I_DIM / 64);   // 64 x 12
    gateup_kernel<<<grid1, 256, smem_bytes>>>();

    dim3 grid2(T_DIM / 128, H_DIM / 128);  // 64 x 16
    down_kernel<<<grid2, 256, smem_bytes>>>(out);
}

// round 7
// speedup vs baseline: 1.9905x; 1.2368x over previous
#include <cuda_runtime.h>
#include <cstdint>

// Qwen3MoeMLP: out = down( silu(x @ gate^T) * (x @ up^T) )
// T=8192, H=2048, I=768, fp32. TF32 mma.sync (tcgen05 unavailable: PTX target
// is sm_103 non-'a').
// R7: operands pre-packed in MMA-fragment order by prep kernel ->
//     mainloop is LDS.128/LDS.64 + HMMA only. 3-stage ring, 1 barrier/kt.

#define T_DIM 8192
#define H_DIM 2048
#define I_DIM 768
#define KH8   (H_DIM / 8)     // 256 k8-tiles over H
#define KI8   (I_DIM / 8)     // 96  k8-tiles over I
#define KT1   (H_DIM / 32)    // 64 BK-iterations (gateup)
#define KT2   (I_DIM / 32)    // 24 BK-iterations (down)
#define STAGE 32768           // bytes per pipeline stage (A 16K + B 16K)

// Static device scratch (no allocations allowed).
// A-pack layout:  [mt][kt8][lane][4 floats]  (m16k8 fragments)
// B-pack layout:  [nt][kt8][lane][2 floats]  (n8k8 fragments)
__device__ __align__(256) float g_xa [(size_t)T_DIM * H_DIM];  // X, A-pack
__device__ __align__(256) float g_wgb[(size_t)I_DIM * H_DIM];  // gate_w, B-pack
__device__ __align__(256) float g_wub[(size_t)I_DIM * H_DIM];  // up_w, B-pack
__device__ __align__(256) float g_wdb[(size_t)H_DIM * I_DIM];  // down_w, B-pack
__device__ __align__(256) float g_ha [(size_t)T_DIM * I_DIM];  // h, A-pack

__device__ __forceinline__ float f2tf(float f) {
    unsigned u;
    asm("cvt.rna.tf32.f32 %0, %1;" : "=r"(u) : "f"(f));
    return __uint_as_float(u);
}
__device__ __forceinline__ void cp16(uint32_t s, const void* g) {
    asm volatile("cp.async.cg.shared.global [%0], [%1], 16;\n" :: "r"(s), "l"(g));
}
__device__ __forceinline__ void cp_commit() {
    asm volatile("cp.async.commit_group;\n" ::);
}
template <int N>
__device__ __forceinline__ void cp_wait() {
    asm volatile("cp.async.wait_group %0;\n" :: "n"(N));
}
__device__ __forceinline__ uint4 lds128(uint32_t a) {
    uint4 v;
    asm volatile("ld.shared.v4.b32 {%0,%1,%2,%3}, [%4];"
                 : "=r"(v.x), "=r"(v.y), "=r"(v.z), "=r"(v.w) : "r"(a));
    return v;
}
__device__ __forceinline__ uint2 lds64(uint32_t a) {
    uint2 v;
    asm volatile("ld.shared.v2.b32 {%0,%1}, [%2];" : "=r"(v.x), "=r"(v.y) : "r"(a));
    return v;
}
__device__ __forceinline__ void mma8(float* c, const uint4 a, const uint2 b) {
    asm volatile(
        "mma.sync.aligned.m16n8k8.row.col.f32.tf32.tf32.f32 "
        "{%0,%1,%2,%3}, {%4,%5,%6,%7}, {%8,%9}, {%0,%1,%2,%3};\n"
        : "+f"(c[0]), "+f"(c[1]), "+f"(c[2]), "+f"(c[3])
        : "r"(a.x), "r"(a.y), "r"(a.z), "r"(a.w), "r"(b.x), "r"(b.y));
}

// ============================================================================
// Prep: round to tf32 grid and pack into fragment order.
// A fragment (m16n8k8 .row A): a0=(g,tg) a1=(g+8,tg) a2=(g,tg+4) a3=(g+8,tg+4)
// B fragment (.col B == W row-major): b0=W[n0+g][k0+tg] b1=W[n0+g][k0+tg+4]
// ============================================================================
__global__ void __launch_bounds__(256)
prep_kernel(const float* __restrict__ X,  const float* __restrict__ Wg,
            const float* __restrict__ Wu, const float* __restrict__ Wd)
{
    const size_t nA = (size_t)(T_DIM / 16) * KH8 * 32;   // X fragments
    const size_t nB = (size_t)(I_DIM / 8)  * KH8 * 32;   // Wg / Wu fragments
    const size_t nD = (size_t)(H_DIM / 8)  * KI8 * 32;   // Wd fragments
    const size_t total = nA + 2 * nB + nD;
    const size_t stride = (size_t)gridDim.x * blockDim.x;

    for (size_t f = (size_t)blockIdx.x * blockDim.x + threadIdx.x; f < total; f += stride) {
        if (f < nA) {
            const int lane = (int)(f & 31);
            const size_t tt = f >> 5;
            const int kt = (int)(tt % KH8);
            const size_t mt = tt / KH8;
            const int gg = lane >> 2, tg = lane & 3;
            const float* s = X + (mt * 16 + gg) * H_DIM + kt * 8 + tg;
            float4 v;
            v.x = f2tf(s[0]);
            v.y = f2tf(s[8 * H_DIM]);
            v.z = f2tf(s[4]);
            v.w = f2tf(s[8 * H_DIM + 4]);
            ((float4*)g_xa)[f] = v;
        } else if (f < nA + 2 * nB) {
            const size_t fb = (f - nA) % nB;
            const float* W  = (f - nA < nB) ? Wg : Wu;
            float* dst      = (f - nA < nB) ? g_wgb : g_wub;
            const int lane = (int)(fb & 31);
            const size_t tt = fb >> 5;
            const int kt = (int)(tt % KH8);
            const size_t nt = tt / KH8;
            const int gg = lane >> 2, tg = lane & 3;
            const float* s = W + (nt * 8 + gg) * H_DIM + kt * 8 + tg;
            float2 v;
            v.x = f2tf(s[0]);
            v.y = f2tf(s[4]);
            ((float2*)dst)[fb] = v;
        } else {
            const size_t fb = f - nA - 2 * nB;
            const int lane = (int)(fb & 31);
            const size_t tt = fb >> 5;
            const int kt = (int)(tt % KI8);
            const size_t nt = tt / KI8;
            const int gg = lane >> 2, tg = lane & 3;
            const float* s = Wd + (nt * 8 + gg) * I_DIM + kt * 8 + tg;
            float2 v;
            v.x = f2tf(s[0]);
            v.y = f2tf(s[4]);
            ((float2*)g_wdb)[fb] = v;
        }
    }
}

// ============================================================================
// Kernel 1: gate+up fused. C tile 128 x 64 per projection.
// Stage: A 16KB [8mt][4k8][32][16B] | Bg 8KB | Bu 8KB  = 32KB, 3 stages.
// ============================================================================
__global__ void __launch_bounds__(256, 2)
gateup_kernel()
{
    extern __shared__ __align__(16) char smem[];
    const uint32_t sb = (uint32_t)__cvta_generic_to_shared(smem);

    const int tid  = threadIdx.x;
    const int lane = tid & 31;
    const int warp = tid >> 5;
    const int wm = warp & 3;
    const int wn = warp >> 2;
    const int g  = lane >> 2;
    const int tg = lane & 3;

    const int bm = blockIdx.x * 128;
    const int bn = blockIdx.y * 64;
    const size_t mt0 = bm >> 4;   // first m16 tile
    const size_t nt0 = bn >> 3;   // first n8 tile

    float accg[2][4][4];
    float accu[2][4][4];
#pragma unroll
    for (int i = 0; i < 2; i++)
#pragma unroll
        for (int j = 0; j < 4; j++)
#pragma unroll
            for (int k = 0; k < 4; k++) { accg[i][j][k] = 0.f; accu[i][j][k] = 0.f; }

    auto load_stage = [&](int s, int kt) {
        const uint32_t st = sb + s * STAGE;
        // A: 1024 x 16B granules
#pragma unroll
        for (int i = 0; i < 4; i++) {
            const int q = tid + 256 * i;
            const int l8 = q & 31, k8 = (q >> 5) & 3, mtl = q >> 7;
            const float* src = g_xa +
                (((mt0 + mtl) * KH8 + (size_t)kt * 4 + k8) * 32 + l8) * 4;
            cp16(st + q * 16, src);
        }
        // Bg/Bu: 512 x 16B granules each (16B = fragments of 2 lanes)
#pragma unroll
        for (int i = 0; i < 2; i++) {
            const int q = tid + 256 * i;
            const int pr = q & 15, k8 = (q >> 4) & 3, ntl = q >> 6;
            const size_t off =
                (((nt0 + ntl) * KH8 + (size_t)kt * 4 + k8) * 32) * 2 + pr * 4;
            cp16(st + 16384 + q * 16, g_wgb + off);
            cp16(st + 24576 + q * 16, g_wub + off);
        }
    };

    auto compute = [&](int s) {
        const uint32_t sa = sb + s * STAGE;
        const uint32_t sg = sa + 16384;
        const uint32_t su = sa + 24576;
#pragma unroll
        for (int k8 = 0; k8 < 4; k8++) {
            uint4 a0 = lds128(sa + (((wm * 2 + 0) * 4 + k8) * 32 + lane) * 16);
            uint4 a1 = lds128(sa + (((wm * 2 + 1) * 4 + k8) * 32 + lane) * 16);
#pragma unroll
            for (int t = 0; t < 4; t++) {
                const int ntl = wn * 4 + t;
                uint2 bg = lds64(sg + ((ntl * 4 + k8) * 32 + lane) * 8);
                uint2 bu = lds64(su + ((ntl * 4 + k8) * 32 + lane) * 8);
                mma8(accg[0][t], a0, bg);
                mma8(accg[1][t], a1, bg);
                mma8(accu[0][t], a0, bu);
                mma8(accu[1][t], a1, bu);
            }
        }
    };

    load_stage(0, 0); cp_commit();
    load_stage(1, 1); cp_commit();

    int sc = 0, sl = 2;
    for (int kt = 0; kt < KT1; ++kt) {
        cp_wait<1>();
        __syncthreads();
        if (kt + 2 < KT1) load_stage(sl, kt + 2);
        cp_commit();
        compute(sc);
        if (++sc == 3) sc = 0;
        if (++sl == 3) sl = 0;
    }

    // Epilogue: h = silu(gate)*up (tf32-rounded), written in A-pack order.
#pragma unroll
    for (int tm = 0; tm < 2; tm++) {
#pragma unroll
        for (int tn = 0; tn < 4; tn++) {
            const size_t mt_h = mt0 + wm * 2 + tm;
            const size_t kt_h = nt0 + wn * 4 + tn;
            float h[4];
#pragma unroll
            for (int i = 0; i < 4; i++) {
                const float gv = accg[tm][tn][i];
                const float uv = accu[tm][tn][i];
                h[i] = f2tf(gv * uv / (1.0f + __expf(-gv)));
            }
            // C frag: c0=(g,2tg) c1=(g,2tg+1) c2=(g+8,2tg) c3=(g+8,2tg+1)
            // A-pack slot: lane' = g*4 + (col&3), j = (row>=8) + 2*(col>=4)
            const int L  = g * 4 + ((2 * tg) & 3);
            const int j0 = (tg >= 2) ? 2 : 0;
            float* base = g_ha + (mt_h * KI8 + kt_h) * 128;   // 32 lanes * 4
            *(float2*)(base + L * 4 + j0)       = make_float2(h[0], h[2]);
            *(float2*)(base + (L + 1) * 4 + j0) = make_float2(h[1], h[3]);
        }
    }
}

// ============================================================================
// Kernel 2: down projection. C tile 128 x 128.
// Stage: A 16KB [8mt][4k8][32][16B] | B 16KB [16nt][4k8][32][8B] = 32KB, 3 st.
// ============================================================================
__global__ void __launch_bounds__(256, 2)
down_kernel(float* __restrict__ Out)
{
    extern __shared__ __align__(16) char smem[];
    const uint32_t sb = (uint32_t)__cvta_generic_to_shared(smem);

    const int tid  = threadIdx.x;
    const int lane = tid & 31;
    const int warp = tid >> 5;
    const int wm = warp & 3;
    const int wn = warp >> 2;
    const int g  = lane >> 2;
    const int tg = lane & 3;

    const int bm = blockIdx.x * 128;
    const int bn = blockIdx.y * 128;
    const size_t mt0 = bm >> 4;
    const size_t nt0 = bn >> 3;

    float acc[2][8][4];
#pragma unroll
    for (int i = 0; i < 2; i++)
#pragma unroll
        for (int j = 0; j < 8; j++)
#pragma unroll
            for (int k = 0; k < 4; k++) acc[i][j][k] = 0.f;

    auto load_stage = [&](int s, int kt) {
        const uint32_t st = sb + s * STAGE;
#pragma unroll
        for (int i = 0; i < 4; i++) {
            const int q = tid + 256 * i;
            const int l8 = q & 31, k8 = (q >> 5) & 3, mtl = q >> 7;
            const float* src = g_ha +
                (((mt0 + mtl) * KI8 + (size_t)kt * 4 + k8) * 32 + l8) * 4;
            cp16(st + q * 16, src);
        }
#pragma unroll
        for (int i = 0; i < 4; i++) {
            const int q = tid + 256 * i;
            const int pr = q & 15, k8 = (q >> 4) & 3, ntl = q >> 6;
            const size_t off =
                (((nt0 + ntl) * KI8 + (size_t)kt * 4 + k8) * 32) * 2 + pr * 4;
            cp16(st + 16384 + q * 16, g_wdb + off);
        }
    };

    auto compute = [&](int s) {
        const uint32_t sa = sb + s * STAGE;
        const uint32_t sB = sa + 16384;
#pragma unroll
        for (int k8 = 0; k8 < 4; k8++) {
            uint4 a0 = lds128(sa + (((wm * 2 + 0) * 4 + k8) * 32 + lane) * 16);
            uint4 a1 = lds128(sa + (((wm * 2 + 1) * 4 + k8) * 32 + lane) * 16);
#pragma unroll
            for (int t = 0; t < 8; t++) {
                const int ntl = wn * 8 + t;
                uint2 b = lds64(sB + ((ntl * 4 + k8) * 32 + lane) * 8);
                mma8(acc[0][t], a0, b);
                mma8(acc[1][t], a1, b);
            }
        }
    };

    load_stage(0, 0); cp_commit();
    load_stage(1, 1); cp_commit();

    int sc = 0, sl = 2;
    for (int kt = 0; kt < KT2; ++kt) {
        cp_wait<1>();
        __syncthreads();
        if (kt + 2 < KT2) load_stage(sl, kt + 2);
        cp_commit();
        compute(sc);
        if (++sc == 3) sc = 0;
        if (++sl == 3) sl = 0;
    }

#pragma unroll
    for (int tm = 0; tm < 2; tm++) {
#pragma unroll
        for (int tn = 0; tn < 8; tn++) {
            const int r0 = bm + wm * 32 + tm * 16 + g;
            const int c0 = bn + wn * 64 + tn * 8 + 2 * tg;
            *(float2*)(Out + (size_t)r0 * H_DIM + c0) =
                make_float2(acc[tm][tn][0], acc[tm][tn][1]);
            *(float2*)(Out + (size_t)(r0 + 8) * H_DIM + c0) =
                make_float2(acc[tm][tn][2], acc[tm][tn][3]);
        }
    }
}

// ============================================================================
// Launch
// ============================================================================
extern "C" void kernel_launch(void* const* d_in, const int* in_sizes, int n_in,
                              void* d_out, int out_size)
{
    const float* x  = (const float*)d_in[0];
    const float* wg = (const float*)d_in[1];
    const float* wu = (const float*)d_in[2];
    const float* wd = (const float*)d_in[3];
    float* out = (float*)d_out;

    const int smem_bytes = 3 * STAGE;   // 98304
    cudaFuncSetAttribute(gateup_kernel, cudaFuncAttributeMaxDynamicSharedMemorySize, smem_bytes);
    cudaFuncSetAttribute(down_kernel,   cudaFuncAttributeMaxDynamicSharedMemorySize, smem_bytes);

    prep_kernel<<<2048, 256>>>(x, wg, wu, wd);

    dim3 grid1(T_DIM / 128, I_DIM / 64);   // 64 x 12
    gateup_kernel<<<grid1, 256, smem_bytes>>>();

    dim3 grid2(T_DIM / 128, H_DIM / 128);  // 64 x 16
    down_kernel<<<grid2, 256, smem_bytes>>>(out);
}

// round 10
// speedup vs baseline: 2.0201x; 1.0148x over previous
#include <cuda_runtime.h>
#include <cstdint>

// Qwen3MoeMLP: out = down( silu(x @ gate^T) * (x @ up^T) )
// T=8192, H=2048, I=768, fp32. TF32 mma.sync (tcgen05 unavailable: PTX target
// is sm_103 non-'a').
// R10: R9 design + fix of the prep indexing bug (`b2 & 767` is NOT `% 768`;
//      768 isn't a power of two -> gate/up weight rows 256..511 were never
//      packed, giving rel_err = sqrt(1/3)).
//   - A operands via LDG.128 from fragment-packed global (register double
//     buffer, no smem traffic for A).
//   - B via 4-stage cp.async ring (16KB/stage).
//   - Gateup = N=128 GEMM with gate/up n8-tiles interleaved -> 64 acc regs,
//     warp-local SiLU pairing. Two stream-ordered kernels.

#define T_DIM 8192
#define H_DIM 2048
#define I_DIM 768
#define KH8   (H_DIM / 8)     // 256 k8-tiles over H
#define KI8   (I_DIM / 8)     // 96  k8-tiles over I
#define KT1   (H_DIM / 32)    // 64 kt-iterations (gateup)
#define KT2   (I_DIM / 32)    // 24 kt-iterations (down)
#define BSTAGE 16384          // B bytes per pipeline stage
#define NSTG   4

// Static device scratch (no allocations allowed).
// A-pack: [mt][k8][lane][4 floats] (m16k8 frags). B-pack: [nt][k8][lane][2 floats].
// g_wgu interleaves gate/up: out_nt = 2q -> gate tile q, 2q+1 -> up tile q.
__device__ __align__(256) float g_xa [(size_t)T_DIM * H_DIM];
__device__ __align__(256) float g_wgu[(size_t)2 * I_DIM * H_DIM];
__device__ __align__(256) float g_wdb[(size_t)H_DIM * I_DIM];
__device__ __align__(256) float g_ha [(size_t)T_DIM * I_DIM];

__device__ __forceinline__ float f2tf(float f) {
    unsigned u;
    asm("cvt.rna.tf32.f32 %0, %1;" : "=r"(u) : "f"(f));
    return __uint_as_float(u);
}
__device__ __forceinline__ float4 round4(float4 v) {
    return make_float4(f2tf(v.x), f2tf(v.y), f2tf(v.z), f2tf(v.w));
}
__device__ __forceinline__ void cp16(uint32_t s, const void* g) {
    asm volatile("cp.async.cg.shared.global [%0], [%1], 16;\n" :: "r"(s), "l"(g));
}
__device__ __forceinline__ void cp_commit() {
    asm volatile("cp.async.commit_group;\n" ::);
}
template <int N>
__device__ __forceinline__ void cp_wait() {
    asm volatile("cp.async.wait_group %0;\n" :: "n"(N));
}
__device__ __forceinline__ uint2 lds64(uint32_t a) {
    uint2 v;
    asm volatile("ld.shared.v2.b32 {%0,%1}, [%2];" : "=r"(v.x), "=r"(v.y) : "r"(a));
    return v;
}
__device__ __forceinline__ void mma8(float* c, const uint4 a, const uint2 b) {
    asm volatile(
        "mma.sync.aligned.m16n8k8.row.col.f32.tf32.tf32.f32 "
        "{%0,%1,%2,%3}, {%4,%5,%6,%7}, {%8,%9}, {%0,%1,%2,%3};\n"
        : "+f"(c[0]), "+f"(c[1]), "+f"(c[2]), "+f"(c[3])
        : "r"(a.x), "r"(a.y), "r"(a.z), "r"(a.w), "r"(b.x), "r"(b.y));
}

// ============================================================================
// Prep: round to tf32 grid, pack to fragment order (coalesced smem staging).
// Blocks [0,2048): X. [2048,3584): Wg/Wu interleaved. [3584,4352): Wd.
// ============================================================================
__global__ void __launch_bounds__(256)
prep_kernel(const float* __restrict__ X,  const float* __restrict__ Wg,
            const float* __restrict__ Wu, const float* __restrict__ Wd)
{
    extern __shared__ float sm[];
    const int tid = threadIdx.x;
    const int bid = blockIdx.x;

    if (bid < 2048) {
        // ---- X -> A-pack ----
        const int mt = bid >> 2;        // 0..511 (m16 tiles)
        const int kc = bid & 3;         // 512-col chunk
        const float* src = X + (size_t)mt * 16 * H_DIM + kc * 512;
#pragma unroll
        for (int i = 0; i < 8; i++) {
            const int q = tid + 256 * i;
            const int r = q >> 7, c4 = q & 127;
            float4 v = round4(__ldg((const float4*)(src + (size_t)r * H_DIM) + c4));
            *(float4*)(sm + r * 516 + c4 * 4) = v;
        }
        __syncthreads();
#pragma unroll
        for (int i = 0; i < 8; i++) {
            const int f = tid + 256 * i;
            const int ktl = f >> 5, lane = f & 31;
            const int g = lane >> 2, tg = lane & 3;
            const int c = ktl * 8 + tg;
            float4 v = make_float4(sm[g * 516 + c],     sm[(g + 8) * 516 + c],
                                   sm[g * 516 + c + 4], sm[(g + 8) * 516 + c + 4]);
            ((float4*)g_xa)[((size_t)mt * KH8 + kc * 64 + ktl) * 32 + lane] = v;
        }
    } else {
        // ---- W -> B-pack ----
        const int b2 = bid - 2048;
        const float* W;
        float* dst;
        int LD, KLD;
        size_t out_nt;
        int kc;
        if (b2 < 1536) {
            const int sel = (b2 < 768) ? 0 : 1;     // 0=gate, 1=up
            W = sel ? Wu : Wg;
            dst = g_wgu;
            LD = H_DIM; KLD = KH8;
            // FIX (R8/R9 bug): 768 is not a power of two; `b2 & 767` dropped
            // bit 8 and left Wg/Wu rows 256..511 unpacked (rel_err sqrt(1/3)).
            const int r = (b2 < 768) ? b2 : b2 - 768;
            const int nt = r >> 3;                  // 0..95
            kc = r & 7;                             // 8 chunks x 256 cols
            out_nt = 2 * (size_t)nt + sel;          // interleave
            W += (size_t)nt * 8 * LD;
        } else {
            W = Wd; dst = g_wdb;
            LD = I_DIM; KLD = KI8;
            const int r = b2 - 1536;
            const int nt = r / 3;                   // 0..255
            kc = r % 3;                             // 3 chunks x 256 cols
            out_nt = (size_t)nt;
            W += (size_t)nt * 8 * LD;
        }
        const float* src = W + kc * 256;
#pragma unroll
        for (int i = 0; i < 2; i++) {
            const int q = tid + 256 * i;
            const int r = q >> 6, c4 = q & 63;
            float4 v = round4(__ldg((const float4*)(src + (size_t)r * LD) + c4));
            *(float4*)(sm + r * 260 + c4 * 4) = v;
        }
        __syncthreads();
#pragma unroll
        for (int i = 0; i < 4; i++) {
            const int f = tid + 256 * i;
            const int ktl = f >> 5, lane = f & 31;
            const int g = lane >> 2, tg = lane & 3;
            const int c = ktl * 8 + tg;
            float2 v = make_float2(sm[g * 260 + c], sm[g * 260 + c + 4]);
            ((float2*)dst)[(out_nt * KLD + kc * 32 + ktl) * 32 + lane] = v;
        }
    }
}

// ============================================================================
// GEMM kernel (shared shape): C tile 128 x 128, mt=2 x nt=8 per warp.
// A via LDG.128 register double-buffer; B via 4-stage cp.async ring.
// GU=true: A=g_xa, B=g_wgu (interleaved), epilogue SiLU-pair -> g_ha (A-pack).
// GU=false: A=g_ha, B=g_wdb, epilogue -> Out.
// ============================================================================
template <int K8S, int KT, bool GU>
__global__ void __launch_bounds__(256, 2)
gemm_kernel(float* __restrict__ Out)
{
    extern __shared__ __align__(16) char smem[];
    const uint32_t sb = (uint32_t)__cvta_generic_to_shared(smem);

    const int tid  = threadIdx.x;
    const int lane = tid & 31;
    const int warp = tid >> 5;
    const int wm = warp & 3;
    const int wn = warp >> 2;
    const int g  = lane >> 2;
    const int tg = lane & 3;

    const int NBN = GU ? 12 : 16;
    const int bmblk = blockIdx.x / NBN;
    const int bnblk = blockIdx.x % NBN;
    const size_t mt0 = (size_t)bmblk * 8;
    const size_t nt0 = (size_t)bnblk * 16;

    const float* Apack = GU ? g_xa : g_ha;
    const float* Bpack = GU ? g_wgu : g_wdb;

    const uint4* ap0 = (const uint4*)Apack + ((mt0 + wm * 2 + 0) * K8S) * 32 + lane;
    const uint4* ap1 = (const uint4*)Apack + ((mt0 + wm * 2 + 1) * K8S) * 32 + lane;

    float acc[2][8][4];
#pragma unroll
    for (int i = 0; i < 2; i++)
#pragma unroll
        for (int j = 0; j < 8; j++)
#pragma unroll
            for (int k = 0; k < 4; k++) acc[i][j][k] = 0.f;

    auto load_B = [&](int s, int kt) {
        const uint32_t st = sb + s * BSTAGE;
#pragma unroll
        for (int i = 0; i < 4; i++) {
            const int q = tid + 256 * i;
            const int pr = q & 15, k8 = (q >> 4) & 3, ntl = q >> 6;
            const float* src = Bpack +
                (((nt0 + ntl) * K8S + (size_t)kt * 4 + k8) * 32) * 2 + pr * 4;
            cp16(st + q * 16, src);
        }
    };

    uint4 a0 = __ldg(ap0);
    uint4 a1 = __ldg(ap1);

    load_B(0, 0); cp_commit();
    load_B(1, 1); cp_commit();
    load_B(2, 2); cp_commit();

    int sc = 0, sl = 3;
    for (int kt = 0; kt < KT; ++kt) {
        cp_wait<2>();
        __syncthreads();
        if (kt + 3 < KT) load_B(sl, kt + 3);
        cp_commit();
        const uint32_t sB = sb + sc * BSTAGE;
#pragma unroll
        for (int k8 = 0; k8 < 4; k8++) {
            int nf = kt * 4 + k8 + 1;
            if (nf > KT * 4 - 1) nf = KT * 4 - 1;
            uint4 n0 = __ldg(ap0 + (size_t)nf * 32);
            uint4 n1 = __ldg(ap1 + (size_t)nf * 32);
#pragma unroll
            for (int t = 0; t < 8; t++) {
                const int ntl = wn * 8 + t;
                uint2 b = lds64(sB + ((ntl * 4 + k8) * 32 + lane) * 8);
                mma8(acc[0][t], a0, b);
                mma8(acc[1][t], a1, b);
            }
            a0 = n0; a1 = n1;
        }
        sc = (sc + 1) & 3;
        sl = (sl + 1) & 3;
    }

    if (GU) {
        // h = silu(gate)*up (tf32-rounded), written in A-pack order.
        // acc[tm][2j] = gate tile q, acc[tm][2j+1] = up tile q,
        // q = bnblk*8 + wn*4 + j.
#pragma unroll
        for (int tm = 0; tm < 2; tm++) {
#pragma unroll
            for (int j = 0; j < 4; j++) {
                const size_t mt_h = mt0 + wm * 2 + tm;
                const size_t kt_h = (size_t)bnblk * 8 + wn * 4 + j;
                float h[4];
#pragma unroll
                for (int i = 0; i < 4; i++) {
                    const float gv = acc[tm][2 * j][i];
                    const float uv = acc[tm][2 * j + 1][i];
                    h[i] = f2tf(gv * uv / (1.0f + __expf(-gv)));
                }
                const int L  = g * 4 + ((2 * tg) & 3);
                const int j0 = (tg >= 2) ? 2 : 0;
                float* base = g_ha + (mt_h * KI8 + kt_h) * 128;
                *(float2*)(base + L * 4 + j0)       = make_float2(h[0], h[2]);
                *(float2*)(base + (L + 1) * 4 + j0) = make_float2(h[1], h[3]);
            }
        }
    } else {
        const int bm = bmblk * 128;
        const int bn = bnblk * 128;
#pragma unroll
        for (int tm = 0; tm < 2; tm++) {
#pragma unroll
            for (int tn = 0; tn < 8; tn++) {
                const int r0 = bm + wm * 32 + tm * 16 + g;
                const int c0 = bn + wn * 64 + tn * 8 + 2 * tg;
                *(float2*)(Out + (size_t)r0 * H_DIM + c0) =
                    make_float2(acc[tm][tn][0], acc[tm][tn][1]);
                *(float2*)(Out + (size_t)(r0 + 8) * H_DIM + c0) =
                    make_float2(acc[tm][tn][2], acc[tm][tn][3]);
            }
        }
    }
}

// ============================================================================
// Launch
// ============================================================================
extern "C" void kernel_launch(void* const* d_in, const int* in_sizes, int n_in,
                              void* d_out, int out_size)
{
    const float* x  = (const float*)d_in[0];
    const float* wg = (const float*)d_in[1];
    const float* wu = (const float*)d_in[2];
    const float* wd = (const float*)d_in[3];
    float* out = (float*)d_out;

    const int prep_smem = 16 * 516 * 4;       // 33024
    const int gemm_smem = NSTG * BSTAGE;      // 65536
    cudaFuncSetAttribute(prep_kernel, cudaFuncAttributeMaxDynamicSharedMemorySize, prep_smem);
    cudaFuncSetAttribute(gemm_kernel<KH8, KT1, true>,
                         cudaFuncAttributeMaxDynamicSharedMemorySize, gemm_smem);
    cudaFuncSetAttribute(gemm_kernel<KI8, KT2, false>,
                         cudaFuncAttributeMaxDynamicSharedMemorySize, gemm_smem);

    prep_kernel<<<4352, 256, prep_smem>>>(x, wg, wu, wd);

    gemm_kernel<KH8, KT1, true ><<<64 * 12, 256, gemm_smem>>>(nullptr);  // gate+up
    gemm_kernel<KI8, KT2, false><<<64 * 16, 256, gemm_smem>>>(out);      // down
}

// round 11
// speedup vs baseline: 2.1075x; 1.0433x over previous
#include <cuda_runtime.h>
#include <cstdint>

// Qwen3MoeMLP: out = down( silu(x @ gate^T) * (x @ up^T) )
// T=8192, H=2048, I=768, fp32. TF32 mma.sync (tcgen05 unavailable: PTX target
// is sm_103 non-'a').
// R11: R10 GEMM cores + single fused GEMM launch (gateup bids [0,768), down
//      bids [768,1792)) with per-rowblock release/acquire counters.
//      R8's identical-looking failure was the prep `& 767` bug (proven by R9
//      failing identically with no counters); fusion itself re-tested here.
//      Down blocks prefetch weight B-stages BEFORE the acquire spin.

#define T_DIM 8192
#define H_DIM 2048
#define I_DIM 768
#define KH8   (H_DIM / 8)     // 256 k8-tiles over H
#define KI8   (I_DIM / 8)     // 96  k8-tiles over I
#define KT1   (H_DIM / 32)    // 64 kt-iterations (gateup)
#define KT2   (I_DIM / 32)    // 24 kt-iterations (down)
#define BSTAGE 16384          // B bytes per pipeline stage
#define NSTG   4
#define GU_BLOCKS 768         // 64 bm x 12 bn (N = 2*I interleaved / 128)
#define DN_BLOCKS 1024        // 64 bm x 16 bn (N = H / 128)

// Static device scratch (no allocations allowed).
// A-pack: [mt][k8][lane][4 floats] (m16k8 frags). B-pack: [nt][k8][lane][2 floats].
// g_wgu interleaves gate/up: out_nt = 2q -> gate tile q, 2q+1 -> up tile q.
__device__ __align__(256) float g_xa [(size_t)T_DIM * H_DIM];
__device__ __align__(256) float g_wgu[(size_t)2 * I_DIM * H_DIM];
__device__ __align__(256) float g_wdb[(size_t)H_DIM * I_DIM];
__device__ __align__(256) float g_ha [(size_t)T_DIM * I_DIM];
__device__ unsigned g_cnt[64];          // rowblock completion counters

__device__ __forceinline__ float f2tf(float f) {
    unsigned u;
    asm("cvt.rna.tf32.f32 %0, %1;" : "=r"(u) : "f"(f));
    return __uint_as_float(u);
}
__device__ __forceinline__ float4 round4(float4 v) {
    return make_float4(f2tf(v.x), f2tf(v.y), f2tf(v.z), f2tf(v.w));
}
__device__ __forceinline__ void cp16(uint32_t s, const void* g) {
    asm volatile("cp.async.cg.shared.global [%0], [%1], 16;\n" :: "r"(s), "l"(g));
}
__device__ __forceinline__ void cp_commit() {
    asm volatile("cp.async.commit_group;\n" ::);
}
template <int N>
__device__ __forceinline__ void cp_wait() {
    asm volatile("cp.async.wait_group %0;\n" :: "n"(N));
}
__device__ __forceinline__ uint2 lds64(uint32_t a) {
    uint2 v;
    asm volatile("ld.shared.v2.b32 {%0,%1}, [%2];" : "=r"(v.x), "=r"(v.y) : "r"(a));
    return v;
}
__device__ __forceinline__ void mma8(float* c, const uint4 a, const uint2 b) {
    asm volatile(
        "mma.sync.aligned.m16n8k8.row.col.f32.tf32.tf32.f32 "
        "{%0,%1,%2,%3}, {%4,%5,%6,%7}, {%8,%9}, {%0,%1,%2,%3};\n"
        : "+f"(c[0]), "+f"(c[1]), "+f"(c[2]), "+f"(c[3])
        : "r"(a.x), "r"(a.y), "r"(a.z), "r"(a.w), "r"(b.x), "r"(b.y));
}

// ============================================================================
// Prep: round to tf32 grid, pack to fragment order (coalesced smem staging).
// Blocks [0,2048): X. [2048,3584): Wg/Wu interleaved. [3584,4352): Wd.
// Also resets rowblock counters (graph replays reuse them).
// ============================================================================
__global__ void __launch_bounds__(256)
prep_kernel(const float* __restrict__ X,  const float* __restrict__ Wg,
            const float* __restrict__ Wu, const float* __restrict__ Wd)
{
    extern __shared__ float sm[];
    const int tid = threadIdx.x;
    const int bid = blockIdx.x;

    if (bid == 0 && tid < 64) g_cnt[tid] = 0;

    if (bid < 2048) {
        // ---- X -> A-pack ----
        const int mt = bid >> 2;        // 0..511 (m16 tiles)
        const int kc = bid & 3;         // 512-col chunk
        const float* src = X + (size_t)mt * 16 * H_DIM + kc * 512;
#pragma unroll
        for (int i = 0; i < 8; i++) {
            const int q = tid + 256 * i;
            const int r = q >> 7, c4 = q & 127;
            float4 v = round4(__ldg((const float4*)(src + (size_t)r * H_DIM) + c4));
            *(float4*)(sm + r * 516 + c4 * 4) = v;
        }
        __syncthreads();
#pragma unroll
        for (int i = 0; i < 8; i++) {
            const int f = tid + 256 * i;
            const int ktl = f >> 5, lane = f & 31;
            const int g = lane >> 2, tg = lane & 3;
            const int c = ktl * 8 + tg;
            float4 v = make_float4(sm[g * 516 + c],     sm[(g + 8) * 516 + c],
                                   sm[g * 516 + c + 4], sm[(g + 8) * 516 + c + 4]);
            ((float4*)g_xa)[((size_t)mt * KH8 + kc * 64 + ktl) * 32 + lane] = v;
        }
    } else {
        // ---- W -> B-pack ----
        const int b2 = bid - 2048;
        const float* W;
        float* dst;
        int LD, KLD;
        size_t out_nt;
        int kc;
        if (b2 < 1536) {
            const int sel = (b2 < 768) ? 0 : 1;     // 0=gate, 1=up
            W = sel ? Wu : Wg;
            dst = g_wgu;
            LD = H_DIM; KLD = KH8;
            const int r = (b2 < 768) ? b2 : b2 - 768;   // NOT & 767 (768 != 2^n)
            const int nt = r >> 3;                  // 0..95
            kc = r & 7;                             // 8 chunks x 256 cols
            out_nt = 2 * (size_t)nt + sel;          // interleave
            W += (size_t)nt * 8 * LD;
        } else {
            W = Wd; dst = g_wdb;
            LD = I_DIM; KLD = KI8;
            const int r = b2 - 1536;
            const int nt = r / 3;                   // 0..255
            kc = r % 3;                             // 3 chunks x 256 cols
            out_nt = (size_t)nt;
            W += (size_t)nt * 8 * LD;
        }
        const float* src = W + kc * 256;
#pragma unroll
        for (int i = 0; i < 2; i++) {
            const int q = tid + 256 * i;
            const int r = q >> 6, c4 = q & 63;
            float4 v = round4(__ldg((const float4*)(src + (size_t)r * LD) + c4));
            *(float4*)(sm + r * 260 + c4 * 4) = v;
        }
        __syncthreads();
#pragma unroll
        for (int i = 0; i < 4; i++) {
            const int f = tid + 256 * i;
            const int ktl = f >> 5, lane = f & 31;
            const int g = lane >> 2, tg = lane & 3;
            const int c = ktl * 8 + tg;
            float2 v = make_float2(sm[g * 260 + c], sm[g * 260 + c + 4]);
            ((float2*)dst)[(out_nt * KLD + kc * 32 + ktl) * 32 + lane] = v;
        }
    }
}

// ============================================================================
// GEMM body (shared shape): C tile 128 x 128, mt=2 x nt=8 per warp.
// A via LDG.128 register double-buffer; B via 4-stage cp.async ring.
// GU: A=g_xa, B=g_wgu (interleaved), SiLU-pair epilogue -> g_ha; release cnt.
// DN: B prefetch first, acquire-spin on cnt, A=g_ha, B=g_wdb -> Out.
// ============================================================================
template <int K8S, int KT, bool GU>
__device__ __forceinline__ void gemm_body(int bid, uint32_t sb, float* __restrict__ Out)
{
    const int tid  = threadIdx.x;
    const int lane = tid & 31;
    const int warp = tid >> 5;
    const int wm = warp & 3;
    const int wn = warp >> 2;
    const int g  = lane >> 2;
    const int tg = lane & 3;

    const int NBN = GU ? 12 : 16;
    const int bmblk = bid / NBN;
    const int bnblk = bid % NBN;
    const size_t mt0 = (size_t)bmblk * 8;
    const size_t nt0 = (size_t)bnblk * 16;

    const float* Apack = GU ? g_xa : g_ha;
    const float* Bpack = GU ? g_wgu : g_wdb;

    auto load_B = [&](int s, int kt) {
        const uint32_t st = sb + s * BSTAGE;
#pragma unroll
        for (int i = 0; i < 4; i++) {
            const int q = tid + 256 * i;
            const int pr = q & 15, k8 = (q >> 4) & 3, ntl = q >> 6;
            const float* src = Bpack +
                (((nt0 + ntl) * K8S + (size_t)kt * 4 + k8) * 32) * 2 + pr * 4;
            cp16(st + q * 16, src);
        }
    };

    // Weight/B prefetch does not depend on gateup output -> issue before acquire.
    load_B(0, 0); cp_commit();
    load_B(1, 1); cp_commit();
    load_B(2, 2); cp_commit();

    if (!GU) {
        // Acquire: wait until all 12 gateup tiles of this rowblock released.
        if (tid == 0) {
            unsigned v;
            const unsigned* p = &g_cnt[bmblk];
            do {
                asm volatile("ld.acquire.gpu.global.u32 %0, [%1];"
                             : "=r"(v) : "l"(p) : "memory");
                if (v < 12u) __nanosleep(128);
            } while (v < 12u);
        }
        __syncthreads();
    }

    const uint4* ap0 = (const uint4*)Apack + ((mt0 + wm * 2 + 0) * K8S) * 32 + lane;
    const uint4* ap1 = (const uint4*)Apack + ((mt0 + wm * 2 + 1) * K8S) * 32 + lane;

    float acc[2][8][4];
#pragma unroll
    for (int i = 0; i < 2; i++)
#pragma unroll
        for (int j = 0; j < 8; j++)
#pragma unroll
            for (int k = 0; k < 4; k++) acc[i][j][k] = 0.f;

    uint4 a0 = __ldg(ap0);
    uint4 a1 = __ldg(ap1);

    int sc = 0, sl = 3;
    for (int kt = 0; kt < KT; ++kt) {
        cp_wait<2>();
        __syncthreads();
        if (kt + 3 < KT) load_B(sl, kt + 3);
        cp_commit();
        const uint32_t sB = sb + sc * BSTAGE;
#pragma unroll
        for (int k8 = 0; k8 < 4; k8++) {
            int nf = kt * 4 + k8 + 1;
            if (nf > KT * 4 - 1) nf = KT * 4 - 1;
            uint4 n0 = __ldg(ap0 + (size_t)nf * 32);
            uint4 n1 = __ldg(ap1 + (size_t)nf * 32);
#pragma unroll
            for (int t = 0; t < 8; t++) {
                const int ntl = wn * 8 + t;
                uint2 b = lds64(sB + ((ntl * 4 + k8) * 32 + lane) * 8);
                mma8(acc[0][t], a0, b);
                mma8(acc[1][t], a1, b);
            }
            a0 = n0; a1 = n1;
        }
        sc = (sc + 1) & 3;
        sl = (sl + 1) & 3;
    }

    if (GU) {
        // h = silu(gate)*up (tf32-rounded), A-pack order.
        // acc[tm][2j]=gate tile q, acc[tm][2j+1]=up tile q, q=bnblk*8+wn*4+j.
#pragma unroll
        for (int tm = 0; tm < 2; tm++) {
#pragma unroll
            for (int j = 0; j < 4; j++) {
                const size_t mt_h = mt0 + wm * 2 + tm;
                const size_t kt_h = (size_t)bnblk * 8 + wn * 4 + j;
                float h[4];
#pragma unroll
                for (int i = 0; i < 4; i++) {
                    const float gv = acc[tm][2 * j][i];
                    const float uv = acc[tm][2 * j + 1][i];
                    h[i] = f2tf(gv * uv / (1.0f + __expf(-gv)));
                }
                const int L  = g * 4 + ((2 * tg) & 3);
                const int j0 = (tg >= 2) ? 2 : 0;
                float* base = g_ha + (mt_h * KI8 + kt_h) * 128;
                *(float2*)(base + L * 4 + j0)       = make_float2(h[0], h[2]);
                *(float2*)(base + (L + 1) * 4 + j0) = make_float2(h[1], h[3]);
            }
        }
        // Release: all stores visible, then bump rowblock counter.
        __threadfence();
        __syncthreads();
        if (tid == 0)
            asm volatile("red.release.gpu.global.add.u32 [%0], %1;"
                         :: "l"(&g_cnt[bmblk]), "r"(1u) : "memory");
    } else {
        const int bm = bmblk * 128;
        const int bn = bnblk * 128;
#pragma unroll
        for (int tm = 0; tm < 2; tm++) {
#pragma unroll
            for (int tn = 0; tn < 8; tn++) {
                const int r0 = bm + wm * 32 + tm * 16 + g;
                const int c0 = bn + wn * 64 + tn * 8 + 2 * tg;
                *(float2*)(Out + (size_t)r0 * H_DIM + c0) =
                    make_float2(acc[tm][tn][0], acc[tm][tn][1]);
                *(float2*)(Out + (size_t)(r0 + 8) * H_DIM + c0) =
                    make_float2(acc[tm][tn][2], acc[tm][tn][3]);
            }
        }
    }
}

__global__ void __launch_bounds__(256, 2)
mlp_kernel(float* __restrict__ Out)
{
    extern __shared__ __align__(16) char smem[];
    const uint32_t sb = (uint32_t)__cvta_generic_to_shared(smem);
    const int bid = blockIdx.x;
    if (bid < GU_BLOCKS) gemm_body<KH8, KT1, true >(bid, sb, Out);
    else                 gemm_body<KI8, KT2, false>(bid - GU_BLOCKS, sb, Out);
}

// ============================================================================
// Launch
// ============================================================================
extern "C" void kernel_launch(void* const* d_in, const int* in_sizes, int n_in,
                              void* d_out, int out_size)
{
    const float* x  = (const float*)d_in[0];
    const float* wg = (const float*)d_in[1];
    const float* wu = (const float*)d_in[2];
    const float* wd = (const float*)d_in[3];
    float* out = (float*)d_out;

    const int prep_smem = 16 * 516 * 4;       // 33024
    const int gemm_smem = NSTG * BSTAGE;      // 65536
    cudaFuncSetAttribute(prep_kernel, cudaFuncAttributeMaxDynamicSharedMemorySize, prep_smem);
    cudaFuncSetAttribute(mlp_kernel,  cudaFuncAttributeMaxDynamicSharedMemorySize, gemm_smem);

    prep_kernel<<<4352, 256, prep_smem>>>(x, wg, wu, wd);
    mlp_kernel<<<GU_BLOCKS + DN_BLOCKS, 256, gemm_smem>>>(out);
}

// round 12
// speedup vs baseline: 2.3041x; 1.0933x over previous
#include <cuda_runtime.h>
#include <cstdint>

// Qwen3MoeMLP: out = down( silu(x @ gate^T) * (x @ up^T) )
// T=8192, H=2048, I=768, fp32. TF32 mma.sync (tcgen05 unavailable: PTX target
// is sm_103 non-'a').
// R12: R11 fused kernel +
//   (1) BK=64 stages (8 k8/kt): per-kt barriers halved (32+12 instead of 64+24)
//   (2) A register prefetch 2 k8 deep (covers ~250cyc L2 latency)

#define T_DIM 8192
#define H_DIM 2048
#define I_DIM 768
#define KH8   (H_DIM / 8)     // 256 k8-tiles over H
#define KI8   (I_DIM / 8)     // 96  k8-tiles over I
#define KT1   (H_DIM / 64)    // 32 kt-iterations (gateup)
#define KT2   (I_DIM / 64)    // 12 kt-iterations (down)
#define BSTAGE 32768          // B bytes per pipeline stage (16 nt x 8 k8 x 256B)
#define NSTG   3
#define GU_BLOCKS 768         // 64 bm x 12 bn (N = 2*I interleaved / 128)
#define DN_BLOCKS 1024        // 64 bm x 16 bn (N = H / 128)

// Static device scratch (no allocations allowed).
// A-pack: [mt][k8][lane][4 floats] (m16k8 frags). B-pack: [nt][k8][lane][2 floats].
// g_wgu interleaves gate/up: out_nt = 2q -> gate tile q, 2q+1 -> up tile q.
__device__ __align__(256) float g_xa [(size_t)T_DIM * H_DIM];
__device__ __align__(256) float g_wgu[(size_t)2 * I_DIM * H_DIM];
__device__ __align__(256) float g_wdb[(size_t)H_DIM * I_DIM];
__device__ __align__(256) float g_ha [(size_t)T_DIM * I_DIM];
__device__ unsigned g_cnt[64];          // rowblock completion counters

__device__ __forceinline__ float f2tf(float f) {
    unsigned u;
    asm("cvt.rna.tf32.f32 %0, %1;" : "=r"(u) : "f"(f));
    return __uint_as_float(u);
}
__device__ __forceinline__ float4 round4(float4 v) {
    return make_float4(f2tf(v.x), f2tf(v.y), f2tf(v.z), f2tf(v.w));
}
__device__ __forceinline__ void cp16(uint32_t s, const void* g) {
    asm volatile("cp.async.cg.shared.global [%0], [%1], 16;\n" :: "r"(s), "l"(g));
}
__device__ __forceinline__ void cp_commit() {
    asm volatile("cp.async.commit_group;\n" ::);
}
template <int N>
__device__ __forceinline__ void cp_wait() {
    asm volatile("cp.async.wait_group %0;\n" :: "n"(N));
}
__device__ __forceinline__ uint2 lds64(uint32_t a) {
    uint2 v;
    asm volatile("ld.shared.v2.b32 {%0,%1}, [%2];" : "=r"(v.x), "=r"(v.y) : "r"(a));
    return v;
}
__device__ __forceinline__ void mma8(float* c, const uint4 a, const uint2 b) {
    asm volatile(
        "mma.sync.aligned.m16n8k8.row.col.f32.tf32.tf32.f32 "
        "{%0,%1,%2,%3}, {%4,%5,%6,%7}, {%8,%9}, {%0,%1,%2,%3};\n"
        : "+f"(c[0]), "+f"(c[1]), "+f"(c[2]), "+f"(c[3])
        : "r"(a.x), "r"(a.y), "r"(a.z), "r"(a.w), "r"(b.x), "r"(b.y));
}

// ============================================================================
// Prep: round to tf32 grid, pack to fragment order (coalesced smem staging).
// Blocks [0,2048): X. [2048,3584): Wg/Wu interleaved. [3584,4352): Wd.
// Also resets rowblock counters (graph replays reuse them).
// ============================================================================
__global__ void __launch_bounds__(256)
prep_kernel(const float* __restrict__ X,  const float* __restrict__ Wg,
            const float* __restrict__ Wu, const float* __restrict__ Wd)
{
    extern __shared__ float sm[];
    const int tid = threadIdx.x;
    const int bid = blockIdx.x;

    if (bid == 0 && tid < 64) g_cnt[tid] = 0;

    if (bid < 2048) {
        // ---- X -> A-pack ----
        const int mt = bid >> 2;        // 0..511 (m16 tiles)
        const int kc = bid & 3;         // 512-col chunk
        const float* src = X + (size_t)mt * 16 * H_DIM + kc * 512;
#pragma unroll
        for (int i = 0; i < 8; i++) {
            const int q = tid + 256 * i;
            const int r = q >> 7, c4 = q & 127;
            float4 v = round4(__ldg((const float4*)(src + (size_t)r * H_DIM) + c4));
            *(float4*)(sm + r * 516 + c4 * 4) = v;
        }
        __syncthreads();
#pragma unroll
        for (int i = 0; i < 8; i++) {
            const int f = tid + 256 * i;
            const int ktl = f >> 5, lane = f & 31;
            const int g = lane >> 2, tg = lane & 3;
            const int c = ktl * 8 + tg;
            float4 v = make_float4(sm[g * 516 + c],     sm[(g + 8) * 516 + c],
                                   sm[g * 516 + c + 4], sm[(g + 8) * 516 + c + 4]);
            ((float4*)g_xa)[((size_t)mt * KH8 + kc * 64 + ktl) * 32 + lane] = v;
        }
    } else {
        // ---- W -> B-pack ----
        const int b2 = bid - 2048;
        const float* W;
        float* dst;
        int LD, KLD;
        size_t out_nt;
        int kc;
        if (b2 < 1536) {
            const int sel = (b2 < 768) ? 0 : 1;     // 0=gate, 1=up
            W = sel ? Wu : Wg;
            dst = g_wgu;
            LD = H_DIM; KLD = KH8;
            const int r = (b2 < 768) ? b2 : b2 - 768;   // NOT & 767 (768 != 2^n)
            const int nt = r >> 3;                  // 0..95
            kc = r & 7;                             // 8 chunks x 256 cols
            out_nt = 2 * (size_t)nt + sel;          // interleave
            W += (size_t)nt * 8 * LD;
        } else {
            W = Wd; dst = g_wdb;
            LD = I_DIM; KLD = KI8;
            const int r = b2 - 1536;
            const int nt = r / 3;                   // 0..255
            kc = r % 3;                             // 3 chunks x 256 cols
            out_nt = (size_t)nt;
            W += (size_t)nt * 8 * LD;
        }
        const float* src = W + kc * 256;
#pragma unroll
        for (int i = 0; i < 2; i++) {
            const int q = tid + 256 * i;
            const int r = q >> 6, c4 = q & 63;
            float4 v = round4(__ldg((const float4*)(src + (size_t)r * LD) + c4));
            *(float4*)(sm + r * 260 + c4 * 4) = v;
        }
        __syncthreads();
#pragma unroll
        for (int i = 0; i < 4; i++) {
            const int f = tid + 256 * i;
            const int ktl = f >> 5, lane = f & 31;
            const int g = lane >> 2, tg = lane & 3;
            const int c = ktl * 8 + tg;
            float2 v = make_float2(sm[g * 260 + c], sm[g * 260 + c + 4]);
            ((float2*)dst)[(out_nt * KLD + kc * 32 + ktl) * 32 + lane] = v;
        }
    }
}

// ============================================================================
// GEMM body: C tile 128 x 128, mt=2 x nt=8 per warp. BK=64 (8 k8) per stage.
// A via LDG.128 register pipeline (2 k8 deep); B via 3-stage cp.async ring.
// GU: A=g_xa, B=g_wgu (interleaved), SiLU-pair epilogue -> g_ha; release cnt.
// DN: B prefetch first, acquire-spin on cnt, A=g_ha, B=g_wdb -> Out.
// ============================================================================
template <int K8S, int KT, bool GU>
__device__ __forceinline__ void gemm_body(int bid, uint32_t sb, float* __restrict__ Out)
{
    const int tid  = threadIdx.x;
    const int lane = tid & 31;
    const int warp = tid >> 5;
    const int wm = warp & 3;
    const int wn = warp >> 2;
    const int g  = lane >> 2;
    const int tg = lane & 3;

    const int NBN = GU ? 12 : 16;
    const int bmblk = bid / NBN;
    const int bnblk = bid % NBN;
    const size_t mt0 = (size_t)bmblk * 8;
    const size_t nt0 = (size_t)bnblk * 16;

    const float* Apack = GU ? g_xa : g_ha;
    const float* Bpack = GU ? g_wgu : g_wdb;

    // Stage layout: [ntl(16)][k8(8)][lane(32)] x 8B = 32KB.
    auto load_B = [&](int s, int kt) {
        const uint32_t st = sb + s * BSTAGE;
#pragma unroll
        for (int i = 0; i < 8; i++) {
            const int q = tid + 256 * i;                 // 0..2047 granules of 16B
            const int pr = q & 15, k8 = (q >> 4) & 7, ntl = q >> 7;
            const float* src = Bpack +
                (((nt0 + ntl) * K8S + (size_t)kt * 8 + k8) * 32) * 2 + pr * 4;
            cp16(st + q * 16, src);
        }
    };

    // Weight/B prefetch does not depend on gateup output -> issue before acquire.
    load_B(0, 0); cp_commit();
    load_B(1, 1); cp_commit();

    if (!GU) {
        // Acquire: wait until all 12 gateup tiles of this rowblock released.
        if (tid == 0) {
            unsigned v;
            const unsigned* p = &g_cnt[bmblk];
            do {
                asm volatile("ld.acquire.gpu.global.u32 %0, [%1];"
                             : "=r"(v) : "l"(p) : "memory");
                if (v < 12u) __nanosleep(128);
            } while (v < 12u);
        }
        __syncthreads();
    }

    const uint4* ap0 = (const uint4*)Apack + ((mt0 + wm * 2 + 0) * K8S) * 32 + lane;
    const uint4* ap1 = (const uint4*)Apack + ((mt0 + wm * 2 + 1) * K8S) * 32 + lane;

    float acc[2][8][4];
#pragma unroll
    for (int i = 0; i < 2; i++)
#pragma unroll
        for (int j = 0; j < 8; j++)
#pragma unroll
            for (int k = 0; k < 4; k++) acc[i][j][k] = 0.f;

    // A register pipeline, 2 k8 deep.
    const int LASTF = KT * 8 - 1;
    uint4 a0 = __ldg(ap0);
    uint4 a1 = __ldg(ap1);
    uint4 b0 = __ldg(ap0 + 32);
    uint4 b1 = __ldg(ap1 + 32);

    int sc = 0, sl = 2;
    for (int kt = 0; kt < KT; ++kt) {
        cp_wait<1>();
        __syncthreads();
        if (kt + 2 < KT) load_B(sl, kt + 2);
        cp_commit();
        const uint32_t sB = sb + sc * BSTAGE;
#pragma unroll
        for (int k8 = 0; k8 < 8; k8++) {
            int nf = kt * 8 + k8 + 2;
            if (nf > LASTF) nf = LASTF;
            uint4 c0 = __ldg(ap0 + (size_t)nf * 32);
            uint4 c1 = __ldg(ap1 + (size_t)nf * 32);
#pragma unroll
            for (int t = 0; t < 8; t++) {
                const int ntl = wn * 8 + t;
                uint2 b = lds64(sB + ((ntl * 8 + k8) * 32 + lane) * 8);
                mma8(acc[0][t], a0, b);
                mma8(acc[1][t], a1, b);
            }
            a0 = b0; a1 = b1; b0 = c0; b1 = c1;
        }
        if (++sc == NSTG) sc = 0;
        if (++sl == NSTG) sl = 0;
    }

    if (GU) {
        // h = silu(gate)*up (tf32-rounded), A-pack order.
        // acc[tm][2j]=gate tile q, acc[tm][2j+1]=up tile q, q=bnblk*8+wn*4+j.
#pragma unroll
        for (int tm = 0; tm < 2; tm++) {
#pragma unroll
            for (int j = 0; j < 4; j++) {
                const size_t mt_h = mt0 + wm * 2 + tm;
                const size_t kt_h = (size_t)bnblk * 8 + wn * 4 + j;
                float h[4];
#pragma unroll
                for (int i = 0; i < 4; i++) {
                    const float gv = acc[tm][2 * j][i];
                    const float uv = acc[tm][2 * j + 1][i];
                    h[i] = f2tf(gv * uv / (1.0f + __expf(-gv)));
                }
                const int L  = g * 4 + ((2 * tg) & 3);
                const int j0 = (tg >= 2) ? 2 : 0;
                float* base = g_ha + (mt_h * KI8 + kt_h) * 128;
                *(float2*)(base + L * 4 + j0)       = make_float2(h[0], h[2]);
                *(float2*)(base + (L + 1) * 4 + j0) = make_float2(h[1], h[3]);
            }
        }
        // Release: all stores visible, then bump rowblock counter.
        __threadfence();
        __syncthreads();
        if (tid == 0)
            asm volatile("red.release.gpu.global.add.u32 [%0], %1;"
                         :: "l"(&g_cnt[bmblk]), "r"(1u) : "memory");
    } else {
        const int bm = bmblk * 128;
        const int bn = bnblk * 128;
#pragma unroll
        for (int tm = 0; tm < 2; tm++) {
#pragma unroll
            for (int tn = 0; tn < 8; tn++) {
                const int r0 = bm + wm * 32 + tm * 16 + g;
                const int c0 = bn + wn * 64 + tn * 8 + 2 * tg;
                *(float2*)(Out + (size_t)r0 * H_DIM + c0) =
                    make_float2(acc[tm][tn][0], acc[tm][tn][1]);
                *(float2*)(Out + (size_t)(r0 + 8) * H_DIM + c0) =
                    make_float2(acc[tm][tn][2], acc[tm][tn][3]);
            }
        }
    }
}

__global__ void __launch_bounds__(256, 2)
mlp_kernel(float* __restrict__ Out)
{
    extern __shared__ __align__(16) char smem[];
    const uint32_t sb = (uint32_t)__cvta_generic_to_shared(smem);
    const int bid = blockIdx.x;
    if (bid < GU_BLOCKS) gemm_body<KH8, KT1, true >(bid, sb, Out);
    else                 gemm_body<KI8, KT2, false>(bid - GU_BLOCKS, sb, Out);
}

// ============================================================================
// Launch
// ============================================================================
extern "C" void kernel_launch(void* const* d_in, const int* in_sizes, int n_in,
                              void* d_out, int out_size)
{
    const float* x  = (const float*)d_in[0];
    const float* wg = (const float*)d_in[1];
    const float* wu = (const float*)d_in[2];
    const float* wd = (const float*)d_in[3];
    float* out = (float*)d_out;

    const int prep_smem = 16 * 516 * 4;       // 33024
    const int gemm_smem = NSTG * BSTAGE;      // 98304
    cudaFuncSetAttribute(prep_kernel, cudaFuncAttributeMaxDynamicSharedMemorySize, prep_smem);
    cudaFuncSetAttribute(mlp_kernel,  cudaFuncAttributeMaxDynamicSharedMemorySize, gemm_smem);

    prep_kernel<<<4352, 256, prep_smem>>>(x, wg, wu, wd);
    mlp_kernel<<<GU_BLOCKS + DN_BLOCKS, 256, gemm_smem>>>(out);
}